// round 2
// baseline (speedup 1.0000x reference)
#include <cuda_runtime.h>
#include <cuda_bf16.h>

#define N_TFH 1000
#define N_TG  20000
#define N_E   4000000

__device__ __forceinline__ float warp_reduce(float v) {
    #pragma unroll
    for (int o = 16; o > 0; o >>= 1)
        v += __shfl_xor_sync(0xFFFFFFFFu, v, o);
    return v;
}

__global__ void zero_out_kernel(float* out) { out[0] = 0.0f; }

// Computes  -(p + q + kterm)  accumulated via block partial sums + atomicAdd.
//   -p     = sum over TF_high of  [0.5*z^2 + log(sigma) + 0.5*log(2pi)]
//   -q     = sum over TG of (fn-1) * logprob(TG_exp; TG_mu, TG_sigma)
//   -kterm = sum over edges of [0.5*dx^2/v + 0.5*log(v) + 0.5*log(2pi)]
// where v = scale^2 = relu(tg_sig^2 - alpha^2*inv_var) + 0.01 (sqrt eliminated).
__global__ __launch_bounds__(256)
void fused_loss_kernel(
    const float* __restrict__ TF_high_mu,
    const float* __restrict__ TF_high_sigma,
    const float* __restrict__ TG_mu,
    const float* __restrict__ TG_sigma,
    const float* __restrict__ TF_high_exp,
    const float* __restrict__ TG_exp,
    const float4* __restrict__ k_edge,
    const float4* __restrict__ alpha,
    const float4* __restrict__ cov,
    const float4* __restrict__ edge_y,
    const float4* __restrict__ edge_x,
    const int*   __restrict__ father_num,
    const int4*  __restrict__ idx_tf_tg,
    const int4*  __restrict__ idx_tf_high,
    const int4*  __restrict__ edge_tg_idx,
    const int4*  __restrict__ is_high,
    float* __restrict__ out)
{
    const float HALF_LOG2PI = 0.918938533204672742f;
    const int tid = blockIdx.x * blockDim.x + threadIdx.x;
    const int NV = N_E / 4;

    float acc = 0.0f;

    if (tid < NV) {
        // Vector loads: 4 edges per thread, fully coalesced 16B accesses.
        float4 ke = k_edge[tid];
        float4 al = alpha[tid];
        float4 cv = cov[tid];
        float4 ey = edge_y[tid];
        float4 ex = edge_x[tid];
        int4  itg = idx_tf_tg[tid];
        int4  ith = idx_tf_high[tid];
        int4  ieg = edge_tg_idx[tid];
        int4  ih  = is_high[tid];

        const float* kef = &ke.x;
        const float* alf = &al.x;
        const float* cvf = &cv.x;
        const float* eyf = &ey.x;
        const float* exf = &ex.x;
        const int*  itgf = &itg.x;
        const int*  ithf = &ith.x;
        const int*  iegf = &ieg.x;
        const int*  ihf  = &ih.x;

        #pragma unroll
        for (int l = 0; l < 4; l++) {
            bool hi = ihf[l] != 0;
            int tf_idx = hi ? ithf[l] : itgf[l];
            const float* mu_tab  = hi ? TF_high_mu    : TG_mu;
            const float* sig_tab = hi ? TF_high_sigma : TG_sigma;
            float tf_mu  = __ldg(mu_tab  + tf_idx);
            float tf_sig = __ldg(sig_tab + tf_idx);
            int gi = iegf[l];
            float tg_mu  = __ldg(TG_mu    + gi);
            float tg_sig = __ldg(TG_sigma + gi);

            float inv_var = __frcp_rn(tf_sig * tf_sig);
            float loc = tg_mu + kef[l] * cvf[l] * (eyf[l] - tf_mu) * inv_var;
            loc = fmaxf(loc, 0.0f) + 0.01f;
            float v = tg_sig * tg_sig - alf[l] * alf[l] * inv_var;
            v = fmaxf(v, 0.0f) + 0.01f;

            float dx = exf[l] - loc;
            // -logprob = 0.5*dx^2/v + 0.5*log(v) + 0.5*log(2pi)
            acc += 0.5f * (dx * dx * __frcp_rn(v) + __logf(v)) + HALF_LOG2PI;
        }
    }

    // q term: -(fn-1)*logprob summed, contributing +(fn-1)*logprob to -(p+q+k)... 
    // final = -(p+q+kterm); q = -sum((fn-1)*lp) so -q = +sum((fn-1)*lp).
    if (tid < N_TG) {
        float mu = TG_mu[tid], sig = TG_sigma[tid], x = TG_exp[tid];
        float fn = (float)father_num[tid];
        float z = (x - mu) / sig;
        float lp = -0.5f * z * z - __logf(sig) - HALF_LOG2PI;
        acc += (fn - 1.0f) * lp;
    }

    // p term: -p contribution.
    if (tid < N_TFH) {
        float mu = TF_high_mu[tid], sig = TF_high_sigma[tid], x = TF_high_exp[tid];
        float z = (x - mu) / sig;
        acc += 0.5f * z * z + __logf(sig) + HALF_LOG2PI;
    }

    // Block reduction: warp shuffle -> smem -> warp 0 -> one atomic per block.
    acc = warp_reduce(acc);
    __shared__ float warp_sums[8];
    int lane = threadIdx.x & 31;
    int wid  = threadIdx.x >> 5;
    if (lane == 0) warp_sums[wid] = acc;
    __syncthreads();
    if (wid == 0) {
        float v = (lane < 8) ? warp_sums[lane] : 0.0f;
        v = warp_reduce(v);
        if (lane == 0) atomicAdd(out, v);
    }
}

extern "C" void kernel_launch(void* const* d_in, const int* in_sizes, int n_in,
                              void* d_out, int out_size) {
    const float* TF_high_mu    = (const float*)d_in[0];
    const float* TF_high_sigma = (const float*)d_in[1];
    const float* TG_mu         = (const float*)d_in[2];
    const float* TG_sigma      = (const float*)d_in[3];
    const float* TF_high_exp   = (const float*)d_in[4];
    const float* TG_exp        = (const float*)d_in[5];
    const float4* k_edge       = (const float4*)d_in[6];
    const float4* alpha        = (const float4*)d_in[7];
    const float4* cov          = (const float4*)d_in[8];
    const float4* edge_y       = (const float4*)d_in[9];
    const float4* edge_x       = (const float4*)d_in[10];
    const int*  father_num     = (const int*)d_in[11];
    const int4* idx_tf_tg      = (const int4*)d_in[12];
    const int4* idx_tf_high    = (const int4*)d_in[13];
    const int4* edge_tg_idx    = (const int4*)d_in[14];
    const int4* is_high        = (const int4*)d_in[15];
    float* out = (float*)d_out;

    zero_out_kernel<<<1, 1>>>(out);

    const int NV = N_E / 4;              // 1,000,000 vector groups
    const int threads = 256;
    const int blocks = (NV + threads - 1) / threads;   // 3907
    fused_loss_kernel<<<blocks, threads>>>(
        TF_high_mu, TF_high_sigma, TG_mu, TG_sigma, TF_high_exp, TG_exp,
        k_edge, alpha, cov, edge_y, edge_x,
        father_num, idx_tf_tg, idx_tf_high, edge_tg_idx, is_high, out);
}